// round 7
// baseline (speedup 1.0000x reference)
#include <cuda_runtime.h>

#define B_TOT 2048
#define H     51
#define RP    56           // padded rows & cols (floats); rows/cols 51..55 zero
#define KU    14           // u2 units per row (RP/4)
#define MSZ   (RP*RP)      // 3136 floats per gate matrix
#define E     16
#define TPB   448          // kh(2) * eg(4) * jrow(56) = 14 warps
#define XCH   40

typedef unsigned long long ull;

struct __align__(16) Smem {
    float l1r[MSZ], l1z[MSZ], l1n[MSZ];   // w_hh1 gates [row][col]
    float ir2[MSZ], iz2[MSZ], in2[MSZ];   // w_ih2
    float hr2[MSZ], hz2[MSZ], hn2[MSZ];   // w_hh2
    float wih1r[RP], wih1z[RP], wih1n[RP];
    float bR1[RP], bZ1[RP], bIN1[RP], bHN1[RP];
    float bR2[RP], bZ2[RP], bIN2[RP], bHN2[RP];
    float wlin[RP];
    float h1[2][E][RP];                   // ping-pong, pads stay 0
    float h2[2][E][RP];
    float xbuf[E][XCH];
    float outp[E];
    float blin;
};

__device__ __forceinline__ void fma2(ull& d, ull a, ull b) {
    asm("fma.rn.f32x2 %0, %1, %2, %0;" : "+l"(d) : "l"(a), "l"(b));
}
__device__ __forceinline__ ull pack2(float a, float b) {
    ull r; asm("mov.b64 %0, {%1,%2};" : "=l"(r) : "f"(a), "f"(b)); return r;
}
__device__ __forceinline__ float sum2(ull v) {
    float a, b; asm("mov.b64 {%0,%1}, %2;" : "=f"(a), "=f"(b) : "l"(v));
    return a + b;
}
__device__ __forceinline__ float sigmoid_(float v) {
    return __fdividef(1.0f, 1.0f + __expf(-v));
}
__device__ __forceinline__ float tanh_(float v) {
    return __fdividef(2.0f, 1.0f + __expf(-2.0f * v)) - 1.0f;
}
__device__ __forceinline__ float gru_cell(float gr, float gz, float gin,
                                          float ghn, float ho) {
    float r = sigmoid_(gr);
    float z = sigmoid_(gz);
    float n = tanh_(fmaf(r, ghn, gin));
    return fmaf(z, ho - n, n);
}
// lane kh keeps ei = 2kh+q, receives partner's half via one float shfl
#define XRED2(g0, g1, sv)                                                    \
    {                                                                        \
        float _s0 = sum2(sv[0]), _s1 = sum2(sv[1]);                          \
        float _s2 = sum2(sv[2]), _s3 = sum2(sv[3]);                          \
        float _ka = kh ? _s2 : _s0, _kb = kh ? _s3 : _s1;                    \
        float _sa = kh ? _s0 : _s2, _sb = kh ? _s1 : _s3;                    \
        g0 = _ka + __shfl_xor_sync(0xFFFFFFFFu, _sa, 1);                     \
        g1 = _kb + __shfl_xor_sync(0xFFFFFFFFu, _sb, 1);                     \
    }

__global__ void __launch_bounds__(TPB, 1) gru_stack_kernel(
    const float* __restrict__ x,
    const float* __restrict__ w_ih1, const float* __restrict__ w_hh1,
    const float* __restrict__ b_ih1, const float* __restrict__ b_hh1,
    const float* __restrict__ w_ih2, const float* __restrict__ w_hh2,
    const float* __restrict__ b_ih2, const float* __restrict__ b_hh2,
    const float* __restrict__ w_lin, const float* __restrict__ b_lin,
    float* __restrict__ out, int T, int F)
{
    extern __shared__ float smem_f[];
    Smem* s = reinterpret_cast<Smem*>(smem_f);

    const int tid = threadIdx.x;
    const int kh  = tid & 1;                // k-half
    const int eg  = (tid >> 1) & 3;         // element group
    const int jr  = tid >> 3;               // gate row 0..55
    const int kb  = kh * 7;                 // u2 offset of k-half
    const int e0  = eg + 8 * kh;            // finalized element 0 (ei = 2kh)
    const int e1  = e0 + 4;                 // finalized element 1 (ei = 2kh+1)
    const int base = blockIdx.x * E;
    const int TF   = T + F;

    // ---------------- one-time init ----------------
    for (int idx = tid; idx < MSZ; idx += TPB) {
        int j = idx / RP, k = idx - j * RP;
        bool valid = (j < H) && (k < H);
        int o = valid ? (j * H + k) : 0;
        s->l1r[idx] = valid ? w_hh1[o] : 0.f;
        s->l1z[idx] = valid ? w_hh1[H * H + o] : 0.f;
        s->l1n[idx] = valid ? w_hh1[2 * H * H + o] : 0.f;
        s->ir2[idx] = valid ? w_ih2[o] : 0.f;
        s->iz2[idx] = valid ? w_ih2[H * H + o] : 0.f;
        s->in2[idx] = valid ? w_ih2[2 * H * H + o] : 0.f;
        s->hr2[idx] = valid ? w_hh2[o] : 0.f;
        s->hz2[idx] = valid ? w_hh2[H * H + o] : 0.f;
        s->hn2[idx] = valid ? w_hh2[2 * H * H + o] : 0.f;
    }
    for (int i = tid; i < RP; i += TPB) {
        bool v = (i < H);
        s->wih1r[i] = v ? w_ih1[i] : 0.f;
        s->wih1z[i] = v ? w_ih1[H + i] : 0.f;
        s->wih1n[i] = v ? w_ih1[2 * H + i] : 0.f;
        s->bR1[i]  = v ? (b_ih1[i] + b_hh1[i]) : 0.f;
        s->bZ1[i]  = v ? (b_ih1[H + i] + b_hh1[H + i]) : 0.f;
        s->bIN1[i] = v ? b_ih1[2 * H + i] : 0.f;
        s->bHN1[i] = v ? b_hh1[2 * H + i] : 0.f;
        s->bR2[i]  = v ? (b_ih2[i] + b_hh2[i]) : 0.f;
        s->bZ2[i]  = v ? (b_ih2[H + i] + b_hh2[H + i]) : 0.f;
        s->bIN2[i] = v ? b_ih2[2 * H + i] : 0.f;
        s->bHN2[i] = v ? b_hh2[2 * H + i] : 0.f;
        s->wlin[i] = v ? w_lin[i] : 0.f;
    }
    if (tid == 0) s->blin = b_lin[0];
    {
        float* h1f = &s->h1[0][0][0];
        float* h2f = &s->h2[0][0][0];
        for (int i = tid; i < 2 * E * RP; i += TPB) { h1f[i] = 0.f; h2f[i] = 0.f; }
        for (int i = tid; i < E; i += TPB) s->outp[i] = 0.f;
    }
    __syncthreads();

    int cur = 0;
    for (int t = 0; t < TF; ++t) {
        if (t < T && (t % XCH) == 0) {
            for (int i = tid; i < E * XCH; i += TPB) {
                int e = i / XCH, c = i - e * XCH;
                int tg = t + c;
                s->xbuf[e][c] = (tg < T) ? x[(size_t)(base + e) * T + tg] : 0.f;
            }
            __syncthreads();
        }
        const int xidx = t % XCH;
        const int nxt = cur ^ 1;

        // -------- output linear for step t-1 (overlaps L1 in phase 1) --------
        if (t > 0 && tid < E) {
            const ulonglong2* hv = (const ulonglong2*)&s->h2[cur][tid][0];
            const ulonglong2* wl = (const ulonglong2*)s->wlin;
            ull acc = pack2(s->blin, 0.f);
            #pragma unroll
            for (int k = 0; k < KU; k++) {
                ulonglong2 h = hv[k], w = wl[k];
                fma2(acc, h.x, w.x); fma2(acc, h.y, w.y);
            }
            float o = sum2(acc);
            out[(size_t)(base + tid) * TF + (t - 1)] = o;
            s->outp[tid] = o;
        }
        if (t >= T) __syncthreads();   // phase 2: outp feeds L1

        // ================= layer 1 =================
        {
            ull aR[4], aZ[4], aN[4];
            #pragma unroll
            for (int ei = 0; ei < 4; ei++) {
                aR[ei] = (kh == 0) ? pack2(s->bR1[jr], 0.f) : 0ull;
                aZ[ei] = (kh == 0) ? pack2(s->bZ1[jr], 0.f) : 0ull;
                aN[ei] = (kh == 0) ? pack2(s->bHN1[jr], 0.f) : 0ull;
            }
            const ulonglong2* wr = (const ulonglong2*)s->l1r + jr * KU + kb;
            const ulonglong2* wz = (const ulonglong2*)s->l1z + jr * KU + kb;
            const ulonglong2* wn = (const ulonglong2*)s->l1n + jr * KU + kb;
            const ulonglong2* ph = (const ulonglong2*)&s->h1[cur][0][0] + eg * KU + kb;
            #pragma unroll
            for (int ki = 0; ki < 7; ki++) {
                ulonglong2 r = wr[ki], z = wz[ki], n = wn[ki];
                #pragma unroll
                for (int ei = 0; ei < 4; ei++) {
                    ulonglong2 h = ph[ki + ei * 4 * KU];
                    fma2(aR[ei], h.x, r.x); fma2(aR[ei], h.y, r.y);
                    fma2(aZ[ei], h.x, z.x); fma2(aZ[ei], h.y, z.y);
                    fma2(aN[ei], h.x, n.x); fma2(aN[ei], h.y, n.y);
                }
            }
            float gR0, gR1, gZ0, gZ1, gN0, gN1;
            XRED2(gR0, gR1, aR);
            XRED2(gZ0, gZ1, aZ);
            XRED2(gN0, gN1, aN);
            const float wr1 = s->wih1r[jr], wz1 = s->wih1z[jr];
            const float wn1 = s->wih1n[jr], bi  = s->bIN1[jr];
            {
                float xv = (t < T) ? s->xbuf[e0][xidx] : s->outp[e0];
                float ho = s->h1[cur][e0][jr];
                s->h1[nxt][e0][jr] = gru_cell(fmaf(xv, wr1, gR0), fmaf(xv, wz1, gZ0),
                                              fmaf(xv, wn1, bi), gN0, ho);
            }
            {
                float xv = (t < T) ? s->xbuf[e1][xidx] : s->outp[e1];
                float ho = s->h1[cur][e1][jr];
                s->h1[nxt][e1][jr] = gru_cell(fmaf(xv, wr1, gR1), fmaf(xv, wz1, gZ1),
                                              fmaf(xv, wn1, bi), gN1, ho);
            }
        }
        __syncthreads();

        // ================= layer 2 =================
        {
            const ulonglong2* pu = (const ulonglong2*)&s->h1[nxt][0][0] + eg * KU + kb;
            const ulonglong2* pv = (const ulonglong2*)&s->h2[cur][0][0] + eg * KU + kb;
            float gR0, gR1, gZ0, gZ1;
            {   // ---- pass RZ ----
                ull aR[4], aZ[4];
                #pragma unroll
                for (int ei = 0; ei < 4; ei++) {
                    aR[ei] = (kh == 0) ? pack2(s->bR2[jr], 0.f) : 0ull;
                    aZ[ei] = (kh == 0) ? pack2(s->bZ2[jr], 0.f) : 0ull;
                }
                const ulonglong2* wir = (const ulonglong2*)s->ir2 + jr * KU + kb;
                const ulonglong2* wiz = (const ulonglong2*)s->iz2 + jr * KU + kb;
                const ulonglong2* whr = (const ulonglong2*)s->hr2 + jr * KU + kb;
                const ulonglong2* whz = (const ulonglong2*)s->hz2 + jr * KU + kb;
                #pragma unroll
                for (int ki = 0; ki < 7; ki++) {
                    ulonglong2 a = wir[ki], b = wiz[ki];
                    ulonglong2 c = whr[ki], d = whz[ki];
                    #pragma unroll
                    for (int ei = 0; ei < 4; ei++) {
                        ulonglong2 u = pu[ki + ei * 4 * KU];
                        ulonglong2 v = pv[ki + ei * 4 * KU];
                        fma2(aR[ei], u.x, a.x); fma2(aR[ei], u.y, a.y);
                        fma2(aR[ei], v.x, c.x); fma2(aR[ei], v.y, c.y);
                        fma2(aZ[ei], u.x, b.x); fma2(aZ[ei], u.y, b.y);
                        fma2(aZ[ei], v.x, d.x); fma2(aZ[ei], v.y, d.y);
                    }
                }
                XRED2(gR0, gR1, aR);
                XRED2(gZ0, gZ1, aZ);
            }
            float gI0, gI1, gH0, gH1;
            {   // ---- pass N ----
                ull aI[4], aH[4];
                #pragma unroll
                for (int ei = 0; ei < 4; ei++) {
                    aI[ei] = (kh == 0) ? pack2(s->bIN2[jr], 0.f) : 0ull;
                    aH[ei] = (kh == 0) ? pack2(s->bHN2[jr], 0.f) : 0ull;
                }
                const ulonglong2* win = (const ulonglong2*)s->in2 + jr * KU + kb;
                const ulonglong2* whn = (const ulonglong2*)s->hn2 + jr * KU + kb;
                #pragma unroll
                for (int ki = 0; ki < 7; ki++) {
                    ulonglong2 a = win[ki], b = whn[ki];
                    #pragma unroll
                    for (int ei = 0; ei < 4; ei++) {
                        ulonglong2 u = pu[ki + ei * 4 * KU];
                        ulonglong2 v = pv[ki + ei * 4 * KU];
                        fma2(aI[ei], u.x, a.x); fma2(aI[ei], u.y, a.y);
                        fma2(aH[ei], v.x, b.x); fma2(aH[ei], v.y, b.y);
                    }
                }
                XRED2(gI0, gI1, aI);
                XRED2(gH0, gH1, aH);
            }
            {
                float ho = s->h2[cur][e0][jr];
                s->h2[nxt][e0][jr] = gru_cell(gR0, gZ0, gI0, gH0, ho);
            }
            {
                float ho = s->h2[cur][e1][jr];
                s->h2[nxt][e1][jr] = gru_cell(gR1, gZ1, gI1, gH1, ho);
            }
        }
        __syncthreads();

        cur = nxt;
    }

    // final output (step TF-1)
    if (tid < E) {
        const ulonglong2* hv = (const ulonglong2*)&s->h2[cur][tid][0];
        const ulonglong2* wl = (const ulonglong2*)s->wlin;
        ull acc = pack2(s->blin, 0.f);
        #pragma unroll
        for (int k = 0; k < KU; k++) {
            ulonglong2 h = hv[k], w = wl[k];
            fma2(acc, h.x, w.x); fma2(acc, h.y, w.y);
        }
        out[(size_t)(base + tid) * TF + (TF - 1)] = sum2(acc);
    }
}

extern "C" void kernel_launch(void* const* d_in, const int* in_sizes, int n_in,
                              void* d_out, int out_size)
{
    const float* x     = (const float*)d_in[0];
    const float* w_ih1 = (const float*)d_in[1];
    const float* w_hh1 = (const float*)d_in[2];
    const float* b_ih1 = (const float*)d_in[3];
    const float* b_hh1 = (const float*)d_in[4];
    const float* w_ih2 = (const float*)d_in[5];
    const float* w_hh2 = (const float*)d_in[6];
    const float* b_ih2 = (const float*)d_in[7];
    const float* b_hh2 = (const float*)d_in[8];
    const float* w_lin = (const float*)d_in[9];
    const float* b_lin = (const float*)d_in[10];

    const int B  = B_TOT;
    const int T  = in_sizes[0] / B;
    const int TF = out_size / B;
    const int F  = TF - T;

    size_t shmem = sizeof(Smem);
    cudaFuncSetAttribute(gru_stack_kernel,
                         cudaFuncAttributeMaxDynamicSharedMemorySize, (int)shmem);

    gru_stack_kernel<<<B / E, TPB, shmem>>>(
        x, w_ih1, w_hh1, b_ih1, b_hh1,
        w_ih2, w_hh2, b_ih2, b_hh2,
        w_lin, b_lin, (float*)d_out, T, F);
}